// round 16
// baseline (speedup 1.0000x reference)
#include <cuda_runtime.h>
#include <cstdint>

#define LOG2E 1.4426950408889634f

// ---------------- scratch ----------------
__device__ float g_Wh[8 * 1024 * 256];   // [b][n][h*32+d]
__device__ float g_e1[64 * 1024];
__device__ float g_e2[64 * 1024];
__device__ float g_maxe2[64];
// B operand, mma-fragment layout: [bh][jp][d*2 + (j&1)], jp = j>>1
__device__ float g_Bhi[64 * 512 * 64];
__device__ float g_Blo[64 * 512 * 64];

// ---------------- helpers ----------------
__device__ __forceinline__ void fma2(unsigned long long& d, unsigned long long a,
                                     unsigned long long b) {
    asm("fma.rn.f32x2 %0, %1, %2, %0;" : "+l"(d) : "l"(a), "l"(b));
}
__device__ __forceinline__ unsigned long long dup2(float v) {
    unsigned long long r;
    asm("mov.b64 %0, {%1,%1};" : "=l"(r) : "f"(v));
    return r;
}
__device__ __forceinline__ void upk2(unsigned long long v, float& lo, float& hi) {
    asm("mov.b64 {%0,%1}, %2;" : "=f"(lo), "=f"(hi) : "l"(v));
}
__device__ __forceinline__ float ex2(float x) {
    float r;
    asm("ex2.approx.ftz.f32 %0, %1;" : "=f"(r) : "f"(x));
    return r;
}
__device__ __forceinline__ float tf32_hi(float x) {
    uint32_t u;
    asm("cvt.rna.tf32.f32 %0, %1;" : "=r"(u) : "f"(x));
    return __uint_as_float(u);
}
__device__ __forceinline__ void mma8(float* c, uint32_t a0, uint32_t a1,
                                     uint32_t a2, uint32_t a3,
                                     uint32_t b0, uint32_t b1) {
    asm volatile(
        "mma.sync.aligned.m16n8k8.row.col.f32.tf32.tf32.f32 "
        "{%0,%1,%2,%3},{%4,%5,%6,%7},{%8,%9},{%0,%1,%2,%3};"
        : "+f"(c[0]), "+f"(c[1]), "+f"(c[2]), "+f"(c[3])
        : "r"(a0), "r"(a1), "r"(a2), "r"(a3), "r"(b0), "r"(b1));
}

// ---------------- kernel 1: Wh = nf @ Wcat; epilogue also emits hi/lo B ----------------
__global__ void __launch_bounds__(256)
gemm_wh_kernel(const float* __restrict__ A, const float* __restrict__ Wm) {
    __shared__ __align__(16) float as[16][132];
    __shared__ __align__(16) float bs[16][64];

    const int row0 = blockIdx.x * 128;
    const int col0 = blockIdx.y * 64;
    const int t = threadIdx.x;
    const int tx = t & 15, ty = t >> 4;

    unsigned long long acc[8][2];
#pragma unroll
    for (int r = 0; r < 8; r++) { acc[r][0] = 0ull; acc[r][1] = 0ull; }

    float4 a_reg[2], b_reg;
    auto load_tile = [&](int k0) {
#pragma unroll
        for (int l = 0; l < 2; l++) {
            int e = t + l * 256;
            int r = e >> 2, kq = e & 3;
            a_reg[l] = *(const float4*)&A[(size_t)(row0 + r) * 256 + k0 + kq * 4];
        }
        {
            int kk = t >> 4, cq = t & 15;
            int c = col0 + cq * 4;
            b_reg = *(const float4*)&Wm[(size_t)(c >> 5) * 8192 +
                                        (size_t)(k0 + kk) * 32 + (c & 31)];
        }
    };

    load_tile(0);
    for (int k0 = 0; k0 < 256; k0 += 16) {
#pragma unroll
        for (int l = 0; l < 2; l++) {
            int e = t + l * 256;
            int r = e >> 2, kq = e & 3;
            as[kq * 4 + 0][r] = a_reg[l].x;
            as[kq * 4 + 1][r] = a_reg[l].y;
            as[kq * 4 + 2][r] = a_reg[l].z;
            as[kq * 4 + 3][r] = a_reg[l].w;
        }
        {
            int kk = t >> 4, cq = t & 15;
            *(float4*)&bs[kk][cq * 4] = b_reg;
        }
        __syncthreads();
        if (k0 + 16 < 256) load_tile(k0 + 16);
#pragma unroll
        for (int kk = 0; kk < 16; kk++) {
            float4 a0 = *(const float4*)&as[kk][ty * 4];
            float4 a1 = *(const float4*)&as[kk][ty * 4 + 64];
            ulonglong2 b0 = *(const ulonglong2*)&bs[kk][tx * 4];
            unsigned long long ad[8];
            ad[0] = dup2(a0.x); ad[1] = dup2(a0.y); ad[2] = dup2(a0.z); ad[3] = dup2(a0.w);
            ad[4] = dup2(a1.x); ad[5] = dup2(a1.y); ad[6] = dup2(a1.z); ad[7] = dup2(a1.w);
#pragma unroll
            for (int r = 0; r < 8; r++) {
                fma2(acc[r][0], b0.x, ad[r]);
                fma2(acc[r][1], b0.y, ad[r]);
            }
        }
        __syncthreads();
    }

    float vals[8][4];
#pragma unroll
    for (int r = 0; r < 8; r++) {
        upk2(acc[r][0], vals[r][0], vals[r][1]);
        upk2(acc[r][1], vals[r][2], vals[r][3]);
        int gr = row0 + ((r < 4) ? (ty * 4 + r) : (64 + ty * 4 + r - 4));
        *(float4*)&g_Wh[(size_t)gr * 256 + col0 + tx * 4] =
            make_float4(vals[r][0], vals[r][1], vals[r][2], vals[r][3]);
    }

    // hi/lo split B in mma fragment layout: [bh][jp][d*2 + parity]
    const int bq = row0 >> 10;
    const int jloc = row0 & 1023;
    const int hh = (col0 >> 5) + (tx >> 3);
    const int d0 = (tx * 4) & 31;
    float* bhp = g_Bhi + (size_t)(bq * 8 + hh) * 32768;
    float* blp = g_Blo + (size_t)(bq * 8 + hh) * 32768;
#pragma unroll
    for (int grp = 0; grp < 2; grp++) {
        int rb = jloc + grp * 64 + ty * 4;
#pragma unroll
        for (int q = 0; q < 2; q++) {
            int jp = (rb >> 1) + q;
            int re = grp * 4 + 2 * q, ro = re + 1;
#pragma unroll
            for (int cI = 0; cI < 4; cI++) {
                float ve = vals[re][cI], vo = vals[ro][cI];
                float he = tf32_hi(ve), ho = tf32_hi(vo);
                int ad = jp * 64 + (d0 + cI) * 2;
                *(float2*)&bhp[ad] = make_float2(he, ho);
                *(float2*)&blp[ad] = make_float2(ve - he, vo - ho);
            }
        }
    }
}

// ---------------- kernel 2: e1, e2, max(e2) per (b,h) ----------------
__global__ void compute_e_kernel(const float* __restrict__ a) {
    const int bh = blockIdx.x;
    const int b = bh >> 3, h = bh & 7;
    const int tid = threadIdx.x;
    const int warp = tid >> 5, lane = tid & 31;

    const float a1v = a[h * 64 + lane];
    const float a2v = a[h * 64 + 32 + lane];
    __shared__ float wmax[8];

    const float* base = g_Wh + (size_t)(b * 1024) * 256 + h * 32;
    float mx = -1e30f;
    for (int nn = 0; nn < 128; nn++) {
        int n = warp * 128 + nn;
        float wh = base[(size_t)n * 256 + lane];
        float x = wh * a1v;
        float y = wh * a2v;
#pragma unroll
        for (int s = 16; s >= 1; s >>= 1) {
            x += __shfl_xor_sync(0xffffffffu, x, s);
            y += __shfl_xor_sync(0xffffffffu, y, s);
        }
        if (lane == 0) {
            g_e1[bh * 1024 + n] = x;
            g_e2[bh * 1024 + n] = y;
        }
        mx = fmaxf(mx, y);
    }
    if (lane == 0) wmax[warp] = mx;
    __syncthreads();
    if (tid == 0) {
        float m = wmax[0];
#pragma unroll
        for (int w = 1; w < 8; w++) m = fmaxf(m, wmax[w]);
        g_maxe2[bh] = m;
    }
}

// ---------------- kernel 3: fused attention, register-direct mma fragments ----------------
// Warp owns 32 i-rows. Permuted j-contraction: thread (g,t) computes p for
// rows {g,g+8,g+16,g+24} x j in [t*8, t*8+8) -> A-fragments directly in regs.
__global__ void __launch_bounds__(512, 1)
gat_attn_mma(const int* __restrict__ adj, const float* __restrict__ bias,
             float* __restrict__ out) {
    __shared__ __align__(16) float e2s[1024];

    const int bh = blockIdx.x >> 1, hv = blockIdx.x & 1;
    const int b = bh >> 3, h = bh & 7;
    const int tid = threadIdx.x, w = tid >> 5, lane = tid & 31;
    const int g = lane >> 2, t = lane & 3;

    for (int n = tid; n < 1024; n += 512) e2s[n] = g_e2[bh * 1024 + n];
    __syncthreads();

    const int i0w = hv * 512 + w * 32;
    const float maxe2 = g_maxe2[bh];

    float e1v[4], mneg[4], sums[4];
#pragma unroll
    for (int ri = 0; ri < 4; ri++) {
        float e = g_e1[bh * 1024 + i0w + ri * 8 + g];
        e1v[ri] = e;
        float s = e + maxe2;
        s = fmaxf(s, 0.2f * s);          // leaky upper bound on all scores of row
        mneg[ri] = -s * LOG2E;
        sums[ri] = 0.0f;
    }

    float c[2][4][4];
#pragma unroll
    for (int mt = 0; mt < 2; mt++)
#pragma unroll
        for (int nt = 0; nt < 4; nt++)
#pragma unroll
            for (int q = 0; q < 4; q++) c[mt][nt][q] = 0.0f;

    const int* adjb = adj + (size_t)(b * 1024 + i0w) * 1024;
    const float* Bhi = g_Bhi + (size_t)bh * 32768;
    const float* Blo = g_Blo + (size_t)bh * 32768;

    // adjacency for tile 0: rows ri*8+g, j in [t*8, t*8+8)
    int ab[4][8];
#pragma unroll
    for (int ri = 0; ri < 4; ri++) {
        *(int4*)&ab[ri][0] = *(const int4*)&adjb[(size_t)(ri * 8 + g) * 1024 + t * 8];
        *(int4*)&ab[ri][4] = *(const int4*)&adjb[(size_t)(ri * 8 + g) * 1024 + t * 8 + 4];
    }

    // B fragments for (jt=0, cc=0)
    uint2 bf[4], lf[4];
#pragma unroll
    for (int nt = 0; nt < 4; nt++) {
        int o = (t * 4) * 64 + (nt * 8 + g) * 2;
        bf[nt] = *(const uint2*)&Bhi[o];
        lf[nt] = *(const uint2*)&Blo[o];
    }

    for (int jt = 0; jt < 32; jt++) {
        const int J0 = jt * 32;
        const int jpb = jt * 16 + t * 4;
#pragma unroll
        for (int cc = 0; cc < 4; cc++) {
            float2 ej = *(const float2*)&e2s[J0 + t * 8 + 2 * cc];
            float ph[4][2], pl[4][2];
#pragma unroll
            for (int ri = 0; ri < 4; ri++) {
#pragma unroll
                for (int par = 0; par < 2; par++) {
                    float s = e1v[ri] + (par ? ej.y : ej.x);
                    s = fmaxf(s, 0.2f * s);
                    float arg = ab[ri][2 * cc + par] ? fmaf(s, LOG2E, mneg[ri])
                                                     : -10000.0f;
                    float pe = ex2(arg);
                    sums[ri] += pe;
                    float hhv = tf32_hi(pe);
                    ph[ri][par] = hhv;
                    pl[ri][par] = pe - hhv;
                }
            }
            // adjacency prefetch for next tile, right after last use of ab
            if (cc == 3 && jt + 1 < 32) {
#pragma unroll
                for (int ri = 0; ri < 4; ri++) {
                    *(int4*)&ab[ri][0] =
                        *(const int4*)&adjb[(size_t)(ri * 8 + g) * 1024 + J0 + 32 + t * 8];
                    *(int4*)&ab[ri][4] =
                        *(const int4*)&adjb[(size_t)(ri * 8 + g) * 1024 + J0 + 32 + t * 8 + 4];
                }
            }
#pragma unroll
            for (int mt = 0; mt < 2; mt++) {
                uint32_t ah0 = __float_as_uint(ph[mt * 2][0]);
                uint32_t ah1 = __float_as_uint(ph[mt * 2 + 1][0]);
                uint32_t ah2 = __float_as_uint(ph[mt * 2][1]);
                uint32_t ah3 = __float_as_uint(ph[mt * 2 + 1][1]);
                uint32_t al0 = __float_as_uint(pl[mt * 2][0]);
                uint32_t al1 = __float_as_uint(pl[mt * 2 + 1][0]);
                uint32_t al2 = __float_as_uint(pl[mt * 2][1]);
                uint32_t al3 = __float_as_uint(pl[mt * 2 + 1][1]);
#pragma unroll
                for (int nt = 0; nt < 4; nt++) {
                    mma8(c[mt][nt], ah0, ah1, ah2, ah3, bf[nt].x, bf[nt].y);
                    mma8(c[mt][nt], al0, al1, al2, al3, bf[nt].x, bf[nt].y);
                    mma8(c[mt][nt], ah0, ah1, ah2, ah3, lf[nt].x, lf[nt].y);
                }
            }
            // B fragment prefetch for next chunk
            if (!(jt == 31 && cc == 3)) {
                int jpn = (cc < 3) ? (jpb + cc + 1) : (jpb + 16);
#pragma unroll
                for (int nt = 0; nt < 4; nt++) {
                    int o = jpn * 64 + (nt * 8 + g) * 2;
                    bf[nt] = *(const uint2*)&Bhi[o];
                    lf[nt] = *(const uint2*)&Blo[o];
                }
            }
        }
    }

    // full row sums: reduce over the 4 t-lanes (all lanes get result)
#pragma unroll
    for (int ri = 0; ri < 4; ri++) {
        float s = sums[ri];
        s += __shfl_xor_sync(0xffffffffu, s, 1);
        s += __shfl_xor_sync(0xffffffffu, s, 2);
        sums[ri] = s;
    }

    // epilogue: normalize, +bias, relu, store
#pragma unroll
    for (int mt = 0; mt < 2; mt++) {
        const float inva = 1.0f / sums[mt * 2];
        const float invb = 1.0f / sums[mt * 2 + 1];
        const int rA = i0w + mt * 16 + g, rB = rA + 8;
#pragma unroll
        for (int nt = 0; nt < 4; nt++) {
            int col = nt * 8 + t * 2;
            float2 bv = *(const float2*)&bias[h * 32 + col];
            float2 oa, ob;
            oa.x = fmaxf(fmaf(c[mt][nt][0], inva, bv.x), 0.0f);
            oa.y = fmaxf(fmaf(c[mt][nt][1], inva, bv.y), 0.0f);
            ob.x = fmaxf(fmaf(c[mt][nt][2], invb, bv.x), 0.0f);
            ob.y = fmaxf(fmaf(c[mt][nt][3], invb, bv.y), 0.0f);
            *(float2*)&out[(size_t)((b << 10) + rA) * 256 + h * 32 + col] = oa;
            *(float2*)&out[(size_t)((b << 10) + rB) * 256 + h * 32 + col] = ob;
        }
    }
}

// ---------------- launch ----------------
extern "C" void kernel_launch(void* const* d_in, const int* in_sizes, int n_in,
                              void* d_out, int out_size) {
    const float* nf   = (const float*)d_in[0];
    const int*   adj  = (const int*)d_in[1];
    const float* Wm   = (const float*)d_in[2];
    const float* av   = (const float*)d_in[3];
    const float* bias = (const float*)d_in[4];
    float* out = (float*)d_out;

    gemm_wh_kernel<<<dim3(64, 4, 1), 256>>>(nf, Wm);
    compute_e_kernel<<<64, 256>>>(av);
    gat_attn_mma<<<128, 512>>>(adj, bias, out);
}

// round 17
// speedup vs baseline: 1.1317x; 1.1317x over previous
#include <cuda_runtime.h>
#include <cstdint>

#define LOG2E 1.4426950408889634f

// ---------------- scratch ----------------
__device__ float g_Wh[8 * 1024 * 256];   // [b][n][h*32+d]
__device__ float g_e1[64 * 1024];
__device__ float g_e2[64 * 1024];
__device__ float g_maxe2[64];
// B operand, mma-fragment layout: [bh][jp][d*2 + (j&1)], jp = j>>1
__device__ float g_Bhi[64 * 512 * 64];
__device__ float g_Blo[64 * 512 * 64];
__device__ uint32_t g_adjp[8 * 1024 * 32];  // bit j%32 of word [row][j/32]

// ---------------- helpers ----------------
__device__ __forceinline__ void fma2(unsigned long long& d, unsigned long long a,
                                     unsigned long long b) {
    asm("fma.rn.f32x2 %0, %1, %2, %0;" : "+l"(d) : "l"(a), "l"(b));
}
__device__ __forceinline__ unsigned long long dup2(float v) {
    unsigned long long r;
    asm("mov.b64 %0, {%1,%1};" : "=l"(r) : "f"(v));
    return r;
}
__device__ __forceinline__ void upk2(unsigned long long v, float& lo, float& hi) {
    asm("mov.b64 {%0,%1}, %2;" : "=f"(lo), "=f"(hi) : "l"(v));
}
__device__ __forceinline__ float ex2(float x) {
    float r;
    asm("ex2.approx.ftz.f32 %0, %1;" : "=f"(r) : "f"(x));
    return r;
}
__device__ __forceinline__ float tf32_hi(float x) {
    uint32_t u;
    asm("cvt.rna.tf32.f32 %0, %1;" : "=r"(u) : "f"(x));
    return __uint_as_float(u);
}
__device__ __forceinline__ void mma8(float* c, uint32_t a0, uint32_t a1,
                                     uint32_t a2, uint32_t a3,
                                     uint32_t b0, uint32_t b1) {
    asm volatile(
        "mma.sync.aligned.m16n8k8.row.col.f32.tf32.tf32.f32 "
        "{%0,%1,%2,%3},{%4,%5,%6,%7},{%8,%9},{%0,%1,%2,%3};"
        : "+f"(c[0]), "+f"(c[1]), "+f"(c[2]), "+f"(c[3])
        : "r"(a0), "r"(a1), "r"(a2), "r"(a3), "r"(b0), "r"(b1));
}

// ---------------- kernel 0: pack adjacency to bits ----------------
__global__ void __launch_bounds__(256)
pack_adj_kernel(const int* __restrict__ adj) {
    int idx = blockIdx.x * 256 + threadIdx.x;   // word index, 262144 total
    int row = idx >> 5, wq = idx & 31;
    const int4* p = (const int4*)(adj + (size_t)row * 1024 + wq * 32);
    uint32_t m = 0;
#pragma unroll
    for (int q = 0; q < 8; q++) {
        int4 v = p[q];
        m |= (v.x != 0 ? 1u : 0u) << (q * 4 + 0);
        m |= (v.y != 0 ? 1u : 0u) << (q * 4 + 1);
        m |= (v.z != 0 ? 1u : 0u) << (q * 4 + 2);
        m |= (v.w != 0 ? 1u : 0u) << (q * 4 + 3);
    }
    g_adjp[idx] = m;
}

// ---------------- kernel 1: Wh = nf @ Wcat; epilogue also emits hi/lo B ----------------
__global__ void __launch_bounds__(256)
gemm_wh_kernel(const float* __restrict__ A, const float* __restrict__ Wm) {
    __shared__ __align__(16) float as[16][132];
    __shared__ __align__(16) float bs[16][64];

    const int row0 = blockIdx.x * 128;
    const int col0 = blockIdx.y * 64;
    const int t = threadIdx.x;
    const int tx = t & 15, ty = t >> 4;

    unsigned long long acc[8][2];
#pragma unroll
    for (int r = 0; r < 8; r++) { acc[r][0] = 0ull; acc[r][1] = 0ull; }

    float4 a_reg[2], b_reg;
    auto load_tile = [&](int k0) {
#pragma unroll
        for (int l = 0; l < 2; l++) {
            int e = t + l * 256;
            int r = e >> 2, kq = e & 3;
            a_reg[l] = *(const float4*)&A[(size_t)(row0 + r) * 256 + k0 + kq * 4];
        }
        {
            int kk = t >> 4, cq = t & 15;
            int c = col0 + cq * 4;
            b_reg = *(const float4*)&Wm[(size_t)(c >> 5) * 8192 +
                                        (size_t)(k0 + kk) * 32 + (c & 31)];
        }
    };

    load_tile(0);
    for (int k0 = 0; k0 < 256; k0 += 16) {
#pragma unroll
        for (int l = 0; l < 2; l++) {
            int e = t + l * 256;
            int r = e >> 2, kq = e & 3;
            as[kq * 4 + 0][r] = a_reg[l].x;
            as[kq * 4 + 1][r] = a_reg[l].y;
            as[kq * 4 + 2][r] = a_reg[l].z;
            as[kq * 4 + 3][r] = a_reg[l].w;
        }
        {
            int kk = t >> 4, cq = t & 15;
            *(float4*)&bs[kk][cq * 4] = b_reg;
        }
        __syncthreads();
        if (k0 + 16 < 256) load_tile(k0 + 16);
#pragma unroll
        for (int kk = 0; kk < 16; kk++) {
            float4 a0 = *(const float4*)&as[kk][ty * 4];
            float4 a1 = *(const float4*)&as[kk][ty * 4 + 64];
            ulonglong2 b0 = *(const ulonglong2*)&bs[kk][tx * 4];
            unsigned long long ad[8];
            ad[0] = dup2(a0.x); ad[1] = dup2(a0.y); ad[2] = dup2(a0.z); ad[3] = dup2(a0.w);
            ad[4] = dup2(a1.x); ad[5] = dup2(a1.y); ad[6] = dup2(a1.z); ad[7] = dup2(a1.w);
#pragma unroll
            for (int r = 0; r < 8; r++) {
                fma2(acc[r][0], b0.x, ad[r]);
                fma2(acc[r][1], b0.y, ad[r]);
            }
        }
        __syncthreads();
    }

    float vals[8][4];
#pragma unroll
    for (int r = 0; r < 8; r++) {
        upk2(acc[r][0], vals[r][0], vals[r][1]);
        upk2(acc[r][1], vals[r][2], vals[r][3]);
        int gr = row0 + ((r < 4) ? (ty * 4 + r) : (64 + ty * 4 + r - 4));
        *(float4*)&g_Wh[(size_t)gr * 256 + col0 + tx * 4] =
            make_float4(vals[r][0], vals[r][1], vals[r][2], vals[r][3]);
    }

    // hi/lo split B in mma fragment layout: [bh][jp][d*2 + parity]
    const int bq = row0 >> 10;
    const int jloc = row0 & 1023;
    const int hh = (col0 >> 5) + (tx >> 3);
    const int d0 = (tx * 4) & 31;
    float* bhp = g_Bhi + (size_t)(bq * 8 + hh) * 32768;
    float* blp = g_Blo + (size_t)(bq * 8 + hh) * 32768;
#pragma unroll
    for (int grp = 0; grp < 2; grp++) {
        int rb = jloc + grp * 64 + ty * 4;
#pragma unroll
        for (int q = 0; q < 2; q++) {
            int jp = (rb >> 1) + q;
            int re = grp * 4 + 2 * q, ro = re + 1;
#pragma unroll
            for (int cI = 0; cI < 4; cI++) {
                float ve = vals[re][cI], vo = vals[ro][cI];
                float he = tf32_hi(ve), ho = tf32_hi(vo);
                int ad = jp * 64 + (d0 + cI) * 2;
                *(float2*)&bhp[ad] = make_float2(he, ho);
                *(float2*)&blp[ad] = make_float2(ve - he, vo - ho);
            }
        }
    }
}

// ---------------- kernel 2: e1, e2, max(e2) per (b,h) ----------------
__global__ void compute_e_kernel(const float* __restrict__ a) {
    const int bh = blockIdx.x;
    const int b = bh >> 3, h = bh & 7;
    const int tid = threadIdx.x;
    const int warp = tid >> 5, lane = tid & 31;

    const float a1v = a[h * 64 + lane];
    const float a2v = a[h * 64 + 32 + lane];
    __shared__ float wmax[8];

    const float* base = g_Wh + (size_t)(b * 1024) * 256 + h * 32;
    float mx = -1e30f;
    for (int nn = 0; nn < 128; nn++) {
        int n = warp * 128 + nn;
        float wh = base[(size_t)n * 256 + lane];
        float x = wh * a1v;
        float y = wh * a2v;
#pragma unroll
        for (int s = 16; s >= 1; s >>= 1) {
            x += __shfl_xor_sync(0xffffffffu, x, s);
            y += __shfl_xor_sync(0xffffffffu, y, s);
        }
        if (lane == 0) {
            g_e1[bh * 1024 + n] = x;
            g_e2[bh * 1024 + n] = y;
        }
        mx = fmaxf(mx, y);
    }
    if (lane == 0) wmax[warp] = mx;
    __syncthreads();
    if (tid == 0) {
        float m = wmax[0];
#pragma unroll
        for (int w = 1; w < 8; w++) m = fmaxf(m, wmax[w]);
        g_maxe2[bh] = m;
    }
}

// ---------------- kernel 3: fused attention, register-direct mma fragments ----------------
// Warp owns 32 i-rows. Permuted j-contraction: thread (g,t) computes p for
// rows {g,g+8,g+16,g+24} x j in [t*8, t*8+8). Adjacency via packed bits.
__global__ void __launch_bounds__(512, 1)
gat_attn_mma(const float* __restrict__ bias, float* __restrict__ out) {
    __shared__ __align__(16) float e2s[1024];

    const int bh = blockIdx.x >> 1, hv = blockIdx.x & 1;
    const int b = bh >> 3, h = bh & 7;
    const int tid = threadIdx.x, w = tid >> 5, lane = tid & 31;
    const int g = lane >> 2, t = lane & 3;
    const int tb = t * 8;               // bit base within word

    for (int n = tid; n < 1024; n += 512) e2s[n] = g_e2[bh * 1024 + n];
    __syncthreads();

    const int i0w = hv * 512 + w * 32;
    const float maxe2 = g_maxe2[bh];

    float e1v[4], mneg[4], sums[4];
#pragma unroll
    for (int ri = 0; ri < 4; ri++) {
        float e = g_e1[bh * 1024 + i0w + ri * 8 + g];
        e1v[ri] = e;
        float s = e + maxe2;
        s = fmaxf(s, 0.2f * s);          // leaky upper bound on all scores of row
        mneg[ri] = -s * LOG2E;
        sums[ri] = 0.0f;
    }

    float c[2][4][4];
#pragma unroll
    for (int mt = 0; mt < 2; mt++)
#pragma unroll
        for (int nt = 0; nt < 4; nt++)
#pragma unroll
            for (int q = 0; q < 4; q++) c[mt][nt][q] = 0.0f;

    const uint32_t* adjw = g_adjp + (size_t)(b * 1024 + i0w) * 32;
    const float* Bhi = g_Bhi + (size_t)bh * 32768;
    const float* Blo = g_Blo + (size_t)bh * 32768;

    // packed adjacency words for tile 0 (word jt of rows ri*8+g)
    uint32_t wb[4];
#pragma unroll
    for (int ri = 0; ri < 4; ri++) wb[ri] = adjw[(ri * 8 + g) * 32];

    // B fragments for (jt=0, cc=0)
    uint2 bf[4], lf[4];
#pragma unroll
    for (int nt = 0; nt < 4; nt++) {
        int o = (t * 4) * 64 + (nt * 8 + g) * 2;
        bf[nt] = *(const uint2*)&Bhi[o];
        lf[nt] = *(const uint2*)&Blo[o];
    }

    for (int jt = 0; jt < 32; jt++) {
        const int J0 = jt * 32;
        const int jpb = jt * 16 + t * 4;
#pragma unroll
        for (int cc = 0; cc < 4; cc++) {
            float2 ej = *(const float2*)&e2s[J0 + tb + 2 * cc];
            float ph[4][2], pl[4][2];
#pragma unroll
            for (int ri = 0; ri < 4; ri++) {
#pragma unroll
                for (int par = 0; par < 2; par++) {
                    float s = e1v[ri] + (par ? ej.y : ej.x);
                    s = fmaxf(s, 0.2f * s);
                    bool on = (wb[ri] >> (tb + 2 * cc + par)) & 1u;
                    float arg = on ? fmaf(s, LOG2E, mneg[ri]) : -10000.0f;
                    float pe = ex2(arg);
                    sums[ri] += pe;
                    float hhv = tf32_hi(pe);
                    ph[ri][par] = hhv;
                    pl[ri][par] = pe - hhv;
                }
            }
            // adjacency word prefetch for next tile, after last use of wb
            if (cc == 3 && jt + 1 < 32) {
#pragma unroll
                for (int ri = 0; ri < 4; ri++)
                    wb[ri] = adjw[(ri * 8 + g) * 32 + jt + 1];
            }
#pragma unroll
            for (int mt = 0; mt < 2; mt++) {
                uint32_t ah0 = __float_as_uint(ph[mt * 2][0]);
                uint32_t ah1 = __float_as_uint(ph[mt * 2 + 1][0]);
                uint32_t ah2 = __float_as_uint(ph[mt * 2][1]);
                uint32_t ah3 = __float_as_uint(ph[mt * 2 + 1][1]);
                uint32_t al0 = __float_as_uint(pl[mt * 2][0]);
                uint32_t al1 = __float_as_uint(pl[mt * 2 + 1][0]);
                uint32_t al2 = __float_as_uint(pl[mt * 2][1]);
                uint32_t al3 = __float_as_uint(pl[mt * 2 + 1][1]);
#pragma unroll
                for (int nt = 0; nt < 4; nt++) {
                    mma8(c[mt][nt], ah0, ah1, ah2, ah3, bf[nt].x, bf[nt].y);
                    mma8(c[mt][nt], al0, al1, al2, al3, bf[nt].x, bf[nt].y);
                    mma8(c[mt][nt], ah0, ah1, ah2, ah3, lf[nt].x, lf[nt].y);
                }
            }
            // B fragment prefetch for next chunk
            if (!(jt == 31 && cc == 3)) {
                int jpn = (cc < 3) ? (jpb + cc + 1) : (jpb + 16);
#pragma unroll
                for (int nt = 0; nt < 4; nt++) {
                    int o = jpn * 64 + (nt * 8 + g) * 2;
                    bf[nt] = *(const uint2*)&Bhi[o];
                    lf[nt] = *(const uint2*)&Blo[o];
                }
            }
        }
    }

    // full row sums: reduce over the 4 t-lanes (all lanes get result)
#pragma unroll
    for (int ri = 0; ri < 4; ri++) {
        float s = sums[ri];
        s += __shfl_xor_sync(0xffffffffu, s, 1);
        s += __shfl_xor_sync(0xffffffffu, s, 2);
        sums[ri] = s;
    }

    // epilogue: normalize, +bias, relu, store
#pragma unroll
    for (int mt = 0; mt < 2; mt++) {
        const float inva = 1.0f / sums[mt * 2];
        const float invb = 1.0f / sums[mt * 2 + 1];
        const int rA = i0w + mt * 16 + g, rB = rA + 8;
#pragma unroll
        for (int nt = 0; nt < 4; nt++) {
            int col = nt * 8 + t * 2;
            float2 bv = *(const float2*)&bias[h * 32 + col];
            float2 oa, ob;
            oa.x = fmaxf(fmaf(c[mt][nt][0], inva, bv.x), 0.0f);
            oa.y = fmaxf(fmaf(c[mt][nt][1], inva, bv.y), 0.0f);
            ob.x = fmaxf(fmaf(c[mt][nt][2], invb, bv.x), 0.0f);
            ob.y = fmaxf(fmaf(c[mt][nt][3], invb, bv.y), 0.0f);
            *(float2*)&out[(size_t)((b << 10) + rA) * 256 + h * 32 + col] = oa;
            *(float2*)&out[(size_t)((b << 10) + rB) * 256 + h * 32 + col] = ob;
        }
    }
}

// ---------------- launch ----------------
extern "C" void kernel_launch(void* const* d_in, const int* in_sizes, int n_in,
                              void* d_out, int out_size) {
    const float* nf   = (const float*)d_in[0];
    const int*   adj  = (const int*)d_in[1];
    const float* Wm   = (const float*)d_in[2];
    const float* av   = (const float*)d_in[3];
    const float* bias = (const float*)d_in[4];
    float* out = (float*)d_out;

    pack_adj_kernel<<<1024, 256>>>(adj);
    gemm_wh_kernel<<<dim3(64, 4, 1), 256>>>(nf, Wm);
    compute_e_kernel<<<64, 256>>>(av);
    gat_attn_mma<<<128, 512>>>(bias, out);
}